// round 5
// baseline (speedup 1.0000x reference)
#include <cuda_runtime.h>
#include <math.h>

// ---------------------------------------------------------------------------
// Problem constants
// B=2, H=W=256, C=256, CD=128, TD=128, HD=32, NH=4, WS=8, SHIFT=4
// PIX = B*H*W = 131072 pixel-tokens. All token tensors are [PIX, ch].
// ---------------------------------------------------------------------------
#define PIX 131072

// Scratch buffers (static device globals; allocation-free per harness rules)
__device__ float g_convx[(size_t)PIX * 128];   // conv path features (pixel order)
__device__ float g_r1[(size_t)PIX * 128];      // conv3x3 intermediate
__device__ float g_tw[(size_t)PIX * 128];      // trans features, window-token order
__device__ float g_h[(size_t)PIX * 128];       // layernorm output (reused ln1/ln2)
__device__ float g_qkv[(size_t)PIX * 384];     // qkv, window-token order
__device__ float g_attnout[(size_t)PIX * 128]; // attention output, window-token order
__device__ float g_t[(size_t)PIX * 128];       // transformer residual stream
__device__ float g_m1[(size_t)PIX * 512];      // mlp hidden

__device__ __forceinline__ float* sel_buf(int s) {
    switch (s) {
        case 1: return g_convx;
        case 2: return g_tw;
        case 3: return g_h;
        case 4: return g_qkv;
        case 5: return g_attnout;
        case 6: return g_t;
        case 7: return g_m1;
        case 8: return g_r1;
        default: return nullptr;
    }
}

// pixel index p = b*65536 + y*256 + x  ->  window-token index after roll(-4,-4)
// token(wi,wj,r,c) corresponds to pixel y=(wi*8+r+4)%256, x=(wj*8+c+4)%256
__device__ __forceinline__ int tok_of_pixel(int p) {
    int b = p >> 16;
    int y = (p >> 8) & 255;
    int x = p & 255;
    int i = (y + 252) & 255;  // (y-4) mod 256
    int j = (x + 252) & 255;
    int wi = i >> 3, r = i & 7;
    int wj = j >> 3, c = j & 7;
    return (((b << 10) | (wi << 5) | wj) << 6) | (r << 3) | c;
}

// ---------------------------------------------------------------------------
// Generic tiled SGEMM: C[M,N] = epilogue(A[M,K] @ W[K,N] + bias)
// BM=BN=128, BK=16, 256 threads, 8x8 per-thread micro-tile.
// gather: 0 = A rows contiguous (stride K); 1 = concat(convx[p], t[tok(p)])
// epi: 0 plain, 1 gelu, 2 +resid, 3 split->convx/tw (conv1), 4 +extra (conv2->out)
// ---------------------------------------------------------------------------
#define GA_NONE   0
#define GA_CONCAT 1
#define EPI_PLAIN 0
#define EPI_GELU  1
#define EPI_RESID 2
#define EPI_SPLIT 3
#define EPI_ADDX  4

__global__ __launch_bounds__(256) void gemm_kernel(
    const float* __restrict__ Aext, int asel,
    const float* __restrict__ W,
    const float* __restrict__ bias,
    const float* __restrict__ Rext, int rsel,
    const float* __restrict__ extra,
    float* __restrict__ Cext, int csel,
    int N, int K, int gather, int epi)
{
    const float* A = asel ? sel_buf(asel) : Aext;
    const float* R = rsel ? sel_buf(rsel) : Rext;
    float* C = csel ? sel_buf(csel) : Cext;

    __shared__ __align__(16) float As[16][132];
    __shared__ __align__(16) float Bs[16][128];

    const int bm = blockIdx.y << 7;
    const int bn = blockIdx.x << 7;
    const int tid = threadIdx.x;
    const int ty = tid >> 4, tx = tid & 15;

    float acc[8][8];
#pragma unroll
    for (int i = 0; i < 8; i++)
#pragma unroll
        for (int j = 0; j < 8; j++) acc[i][j] = 0.f;

    for (int k0 = 0; k0 < K; k0 += 16) {
        // load A tile (128 rows x 16 k), transposed into As[k][m]
#pragma unroll
        for (int l = 0; l < 2; l++) {
            int f = tid + (l << 8);
            int row = f >> 2;
            int kk4 = (f & 3) << 2;
            int m = bm + row;
            int k = k0 + kk4;
            float4 v;
            if (gather == GA_NONE) {
                v = *(const float4*)(A + (size_t)m * K + k);
            } else { // concat: k<128 -> convx[p], else t[tok(p)]
                if (k < 128) {
                    v = *(const float4*)(g_convx + (size_t)m * 128 + k);
                } else {
                    int tk = tok_of_pixel(m);
                    v = *(const float4*)(g_t + (size_t)tk * 128 + (k - 128));
                }
            }
            As[kk4 + 0][row] = v.x;
            As[kk4 + 1][row] = v.y;
            As[kk4 + 2][row] = v.z;
            As[kk4 + 3][row] = v.w;
        }
        // load B tile (16 k x 128 n)
#pragma unroll
        for (int l = 0; l < 2; l++) {
            int f = tid + (l << 8);
            int kk = f >> 5;
            int c4 = (f & 31) << 2;
            *(float4*)&Bs[kk][c4] = *(const float4*)(W + (size_t)(k0 + kk) * N + bn + c4);
        }
        __syncthreads();
#pragma unroll
        for (int kk = 0; kk < 16; kk++) {
            float4 a0 = *(const float4*)&As[kk][ty * 8];
            float4 a1 = *(const float4*)&As[kk][ty * 8 + 4];
            float4 b0 = *(const float4*)&Bs[kk][tx * 8];
            float4 b1 = *(const float4*)&Bs[kk][tx * 8 + 4];
            float a[8] = {a0.x, a0.y, a0.z, a0.w, a1.x, a1.y, a1.z, a1.w};
            float b[8] = {b0.x, b0.y, b0.z, b0.w, b1.x, b1.y, b1.z, b1.w};
#pragma unroll
            for (int i = 0; i < 8; i++)
#pragma unroll
                for (int j = 0; j < 8; j++) acc[i][j] += a[i] * b[j];
        }
        __syncthreads();
    }

    // epilogue
#pragma unroll
    for (int i = 0; i < 8; i++) {
        const int m = bm + ty * 8 + i;
        if (epi == EPI_SPLIT) {
            const size_t twbase = (size_t)tok_of_pixel(m) * 128;
#pragma unroll
            for (int j = 0; j < 8; j++) {
                const int n = bn + tx * 8 + j;
                float v = acc[i][j] + bias[n];
                if (n < 128) g_convx[(size_t)m * 128 + n] = v;
                else         g_tw[twbase + (n - 128)] = v;
            }
        } else {
#pragma unroll
            for (int j = 0; j < 8; j++) {
                const int n = bn + tx * 8 + j;
                float v = acc[i][j] + bias[n];
                const size_t idx = (size_t)m * N + n;
                if (epi == EPI_GELU) {
                    v = 0.5f * v * (1.f + erff(v * 0.70710678118654752f));
                } else if (epi == EPI_RESID) {
                    v += R[idx];
                } else if (epi == EPI_ADDX) {
                    v += extra[idx];
                }
                C[idx] = v;
            }
        }
    }
}

// ---------------------------------------------------------------------------
// 3x3 conv (SAME), implicit GEMM. 128 contiguous pixels per block (all share
// one image row since W=256), all 128 output channels. K-loop = 9 taps x 8
// chunks of 16 input channels. Epilogue: lrelu then optional +scale*resid.
// ---------------------------------------------------------------------------
__global__ __launch_bounds__(256) void conv3_kernel(
    int insel, const float* __restrict__ W,
    const float* __restrict__ bias,
    int rsel, float rscale, int osel)
{
    const float* in = sel_buf(insel);
    const float* R = rsel ? sel_buf(rsel) : nullptr;
    float* out = sel_buf(osel);

    __shared__ __align__(16) float As[16][132];
    __shared__ __align__(16) float Bs[16][128];

    const int bm = blockIdx.x << 7;
    const int b = bm >> 16;
    const int y = (bm >> 8) & 255;
    const int x0 = bm & 255;
    const int tid = threadIdx.x;
    const int ty = tid >> 4, tx = tid & 15;

    float acc[8][8];
#pragma unroll
    for (int i = 0; i < 8; i++)
#pragma unroll
        for (int j = 0; j < 8; j++) acc[i][j] = 0.f;

    for (int tap = 0; tap < 9; tap++) {
        const int dy = tap / 3 - 1;
        const int dx = tap % 3 - 1;
        const int yy = y + dy;
        const bool rowok = ((unsigned)yy < 256u);
        for (int kc = 0; kc < 128; kc += 16) {
#pragma unroll
            for (int l = 0; l < 2; l++) {
                int f = tid + (l << 8);
                int row = f >> 2;
                int kk4 = (f & 3) << 2;
                int xx = x0 + row + dx;
                float4 v = make_float4(0.f, 0.f, 0.f, 0.f);
                if (rowok && (unsigned)xx < 256u) {
                    size_t idx = ((size_t)((b * 256 + yy) * 256 + xx)) * 128 + kc + kk4;
                    v = *(const float4*)(in + idx);
                }
                As[kk4 + 0][row] = v.x;
                As[kk4 + 1][row] = v.y;
                As[kk4 + 2][row] = v.z;
                As[kk4 + 3][row] = v.w;
            }
#pragma unroll
            for (int l = 0; l < 2; l++) {
                int f = tid + (l << 8);
                int kk = f >> 5;
                int c4 = (f & 31) << 2;
                *(float4*)&Bs[kk][c4] =
                    *(const float4*)(W + (size_t)(tap * 128 + kc + kk) * 128 + c4);
            }
            __syncthreads();
#pragma unroll
            for (int kk = 0; kk < 16; kk++) {
                float4 a0 = *(const float4*)&As[kk][ty * 8];
                float4 a1 = *(const float4*)&As[kk][ty * 8 + 4];
                float4 b0 = *(const float4*)&Bs[kk][tx * 8];
                float4 b1 = *(const float4*)&Bs[kk][tx * 8 + 4];
                float a[8] = {a0.x, a0.y, a0.z, a0.w, a1.x, a1.y, a1.z, a1.w};
                float bb[8] = {b0.x, b0.y, b0.z, b0.w, b1.x, b1.y, b1.z, b1.w};
#pragma unroll
                for (int i = 0; i < 8; i++)
#pragma unroll
                    for (int j = 0; j < 8; j++) acc[i][j] += a[i] * bb[j];
            }
            __syncthreads();
        }
    }

#pragma unroll
    for (int i = 0; i < 8; i++) {
        const size_t m = (size_t)bm + ty * 8 + i;
#pragma unroll
        for (int j = 0; j < 8; j++) {
            const int n = tx * 8 + j;
            float v = acc[i][j] + bias[n];
            v = (v >= 0.f) ? v : 0.01f * v;
            if (R) v += rscale * R[m * 128 + n];
            out[m * 128 + n] = v;
        }
    }
}

// ---------------------------------------------------------------------------
// LayerNorm over 128 channels; 1 warp per row, 8 rows per block.
// ---------------------------------------------------------------------------
__global__ __launch_bounds__(256) void ln_kernel(
    int insel, const float* __restrict__ gamma,
    const float* __restrict__ beta, int osel)
{
    const float* in = sel_buf(insel);
    float* out = sel_buf(osel);
    const int row = blockIdx.x * 8 + (threadIdx.x >> 5);
    const int lane = threadIdx.x & 31;
    const float4 v = *(const float4*)(in + (size_t)row * 128 + lane * 4);
    float sum = v.x + v.y + v.z + v.w;
    float sq = v.x * v.x + v.y * v.y + v.z * v.z + v.w * v.w;
#pragma unroll
    for (int off = 16; off > 0; off >>= 1) {
        sum += __shfl_xor_sync(0xffffffffu, sum, off);
        sq  += __shfl_xor_sync(0xffffffffu, sq, off);
    }
    const float mean = sum * 0.0078125f;
    const float var = sq * 0.0078125f - mean * mean;
    const float rstd = rsqrtf(var + 1e-5f);
    const float4 g4 = *(const float4*)(gamma + lane * 4);
    const float4 b4 = *(const float4*)(beta + lane * 4);
    float4 o;
    o.x = (v.x - mean) * rstd * g4.x + b4.x;
    o.y = (v.y - mean) * rstd * g4.y + b4.y;
    o.z = (v.z - mean) * rstd * g4.z + b4.z;
    o.w = (v.w - mean) * rstd * g4.w + b4.w;
    *(float4*)(out + (size_t)row * 128 + lane * 4) = o;
}

// ---------------------------------------------------------------------------
// Windowed attention: 1 block per (batch, window) = 2048 blocks, 256 threads.
// Thread t handles (head = t/64, query = t%64). Scores/softmax in registers;
// K then V staged through the same smem buffer (two phases).
// ---------------------------------------------------------------------------
__global__ __launch_bounds__(256) void attn_kernel(const float* __restrict__ rpb)
{
    __shared__ __align__(16) float skv[64][128];
    __shared__ float srpb[900];

    const int wid = blockIdx.x;          // b*1024 + wi*32 + wj
    const int wi = (wid >> 5) & 31;
    const int wj = wid & 31;
    const size_t tokbase = (size_t)wid * 64;
    const float* qkvp = g_qkv + tokbase * 384;
    const int tid = threadIdx.x;

    // load K (cols 128..255 of qkv)
#pragma unroll
    for (int l = 0; l < 8; l++) {
        int f = tid + (l << 8);
        int j = f >> 5;
        int c4 = (f & 31) << 2;
        *(float4*)&skv[j][c4] = *(const float4*)(qkvp + (size_t)j * 384 + 128 + c4);
    }
    for (int f = tid; f < 900; f += 256) srpb[f] = rpb[f];
    __syncthreads();

    const int head = tid >> 6;
    const int i = tid & 63;
    const int hb = head << 5;

    float q[32];
    {
        const float* qp = qkvp + (size_t)i * 384 + hb;
#pragma unroll
        for (int d4 = 0; d4 < 8; d4++) {
            float4 v = *(const float4*)(qp + 4 * d4);
            q[4 * d4 + 0] = v.x; q[4 * d4 + 1] = v.y;
            q[4 * d4 + 2] = v.z; q[4 * d4 + 3] = v.w;
        }
    }
    const int ri = i >> 3, ci = i & 7;
    const int gi = ((wi == 31) ? (ri < 4 ? 1 : 2) : 0) * 3
                 + ((wj == 31) ? (ci < 4 ? 1 : 2) : 0);

    float s[64];
#pragma unroll
    for (int j = 0; j < 64; j++) {
        float dot = 0.f;
#pragma unroll
        for (int d4 = 0; d4 < 8; d4++) {
            float4 kv = *(const float4*)&skv[j][hb + 4 * d4];
            dot += q[4 * d4 + 0] * kv.x;
            dot += q[4 * d4 + 1] * kv.y;
            dot += q[4 * d4 + 2] * kv.z;
            dot += q[4 * d4 + 3] * kv.w;
        }
        const int rj = j >> 3, cj = j & 7;
        const int gj = ((wi == 31) ? (rj < 4 ? 1 : 2) : 0) * 3
                     + ((wj == 31) ? (cj < 4 ? 1 : 2) : 0);
        const float bias = srpb[((ri - rj + 7) * 15 + (ci - cj + 7)) * 4 + head];
        const float msk = (gi == gj) ? 0.f : -1000000000.f;
        s[j] = dot * 0.17677669529663689f + bias + msk;
    }

    float mx = s[0];
#pragma unroll
    for (int j = 1; j < 64; j++) mx = fmaxf(mx, s[j]);
    float sum = 0.f;
#pragma unroll
    for (int j = 0; j < 64; j++) { s[j] = __expf(s[j] - mx); sum += s[j]; }
    const float inv = 1.f / sum;

    __syncthreads();  // all threads done reading K
    // load V (cols 256..383)
#pragma unroll
    for (int l = 0; l < 8; l++) {
        int f = tid + (l << 8);
        int j = f >> 5;
        int c4 = (f & 31) << 2;
        *(float4*)&skv[j][c4] = *(const float4*)(qkvp + (size_t)j * 384 + 256 + c4);
    }
    __syncthreads();

    float o[32];
#pragma unroll
    for (int d = 0; d < 32; d++) o[d] = 0.f;
#pragma unroll
    for (int j = 0; j < 64; j++) {
        const float a = s[j];
#pragma unroll
        for (int d4 = 0; d4 < 8; d4++) {
            float4 vv = *(const float4*)&skv[j][hb + 4 * d4];
            o[4 * d4 + 0] += a * vv.x;
            o[4 * d4 + 1] += a * vv.y;
            o[4 * d4 + 2] += a * vv.z;
            o[4 * d4 + 3] += a * vv.w;
        }
    }
    float* op = g_attnout + (tokbase + i) * 128 + hb;
#pragma unroll
    for (int d4 = 0; d4 < 8; d4++) {
        float4 v = make_float4(o[4 * d4 + 0] * inv, o[4 * d4 + 1] * inv,
                               o[4 * d4 + 2] * inv, o[4 * d4 + 3] * inv);
        *(float4*)(op + 4 * d4) = v;
    }
}

// ---------------------------------------------------------------------------
// Launch orchestration
// ---------------------------------------------------------------------------
extern "C" void kernel_launch(void* const* d_in, const int* in_sizes, int n_in,
                              void* d_out, int out_size)
{
    (void)in_sizes; (void)n_in; (void)out_size;
    const float* x    = (const float*)d_in[0];
    const float* c1w  = (const float*)d_in[1];
    const float* c1b  = (const float*)d_in[2];
    const float* rw1  = (const float*)d_in[3];
    const float* rb1  = (const float*)d_in[4];
    const float* rw2  = (const float*)d_in[5];
    const float* rb2  = (const float*)d_in[6];
    const float* ln1g = (const float*)d_in[7];
    const float* ln1b = (const float*)d_in[8];
    const float* qkvw = (const float*)d_in[9];
    const float* qkvb = (const float*)d_in[10];
    const float* rpb  = (const float*)d_in[11];
    const float* pw   = (const float*)d_in[12];
    const float* pb   = (const float*)d_in[13];
    const float* ln2g = (const float*)d_in[14];
    const float* ln2b = (const float*)d_in[15];
    const float* mw1  = (const float*)d_in[16];
    const float* mb1  = (const float*)d_in[17];
    const float* mw2  = (const float*)d_in[18];
    const float* mb2  = (const float*)d_in[19];
    const float* c2w  = (const float*)d_in[20];
    const float* c2b  = (const float*)d_in[21];
    float* out = (float*)d_out;

    const dim3 blk(256);
    const int MB = PIX / 128;  // 1024 M-tiles

    // 1. conv1 (1x1): y = x @ c1w + c1b; split -> g_convx (pixel order),
    //    g_tw (window-token order, rolled by -SHIFT)
    gemm_kernel<<<dim3(2, MB), blk>>>(x, 0, c1w, c1b, nullptr, 0, nullptr,
                                      nullptr, 0, 256, 256, GA_NONE, EPI_SPLIT);
    // 2. r1 = lrelu(conv3x3(convx, rw1) + rb1)
    conv3_kernel<<<MB, blk>>>(1, rw1, rb1, 0, 0.f, 8);
    // 3. convx = lrelu(conv3x3(r1, rw2) + rb2) + 2*convx   (in-place residual)
    conv3_kernel<<<MB, blk>>>(8, rw2, rb2, 1, 2.f, 1);
    // 4. h = LN1(tw)
    ln_kernel<<<PIX / 8, blk>>>(2, ln1g, ln1b, 3);
    // 5. qkv = h @ qkvw + qkvb
    gemm_kernel<<<dim3(3, MB), blk>>>(nullptr, 3, qkvw, qkvb, nullptr, 0, nullptr,
                                      nullptr, 4, 384, 128, GA_NONE, EPI_PLAIN);
    // 6. windowed attention -> g_attnout
    attn_kernel<<<2048, blk>>>(rpb);
    // 7. t = attnout @ pw + pb + tw
    gemm_kernel<<<dim3(1, MB), blk>>>(nullptr, 5, pw, pb, nullptr, 2, nullptr,
                                      nullptr, 6, 128, 128, GA_NONE, EPI_RESID);
    // 8. h = LN2(t)
    ln_kernel<<<PIX / 8, blk>>>(6, ln2g, ln2b, 3);
    // 9. m1 = gelu(h @ mw1 + mb1)
    gemm_kernel<<<dim3(4, MB), blk>>>(nullptr, 3, mw1, mb1, nullptr, 0, nullptr,
                                      nullptr, 7, 512, 128, GA_NONE, EPI_GELU);
    // 10. t = m1 @ mw2 + mb2 + t   (in-place, element-wise 1:1, safe)
    gemm_kernel<<<dim3(1, MB), blk>>>(nullptr, 7, mw2, mb2, nullptr, 6, nullptr,
                                      nullptr, 6, 128, 512, GA_NONE, EPI_RESID);
    // 11. out = concat(convx, t[tok(p)]) @ c2w + c2b + x
    gemm_kernel<<<dim3(2, MB), blk>>>(nullptr, 0, c2w, c2b, nullptr, 0, x,
                                      out, 0, 256, 256, GA_CONCAT, EPI_ADDX);
}

// round 6
// speedup vs baseline: 1.0023x; 1.0023x over previous
#include <cuda_runtime.h>
#include <math.h>

// ---------------------------------------------------------------------------
// Problem constants
// B=2, H=W=256, C=256, CD=128, TD=128, HD=32, NH=4, WS=8, SHIFT=4
// PIX = B*H*W = 131072 pixel-tokens. All token tensors are [PIX, ch].
// ---------------------------------------------------------------------------
#define PIX 131072

// Scratch buffers (static device globals; allocation-free per harness rules)
__device__ float g_convx[(size_t)PIX * 128];   // conv path features (pixel order)
__device__ float g_r1[(size_t)PIX * 128];      // conv3x3 intermediate
__device__ float g_tw[(size_t)PIX * 128];      // trans features, window-token order
__device__ float g_h[(size_t)PIX * 128];       // layernorm output (reused ln1/ln2)
__device__ float g_qkv[(size_t)PIX * 384];     // qkv, window-token order
__device__ float g_attnout[(size_t)PIX * 128]; // attention output, window-token order
__device__ float g_t[(size_t)PIX * 128];       // transformer residual stream
__device__ float g_m1[(size_t)PIX * 512];      // mlp hidden

__device__ __forceinline__ float* sel_buf(int s) {
    switch (s) {
        case 1: return g_convx;
        case 2: return g_tw;
        case 3: return g_h;
        case 4: return g_qkv;
        case 5: return g_attnout;
        case 6: return g_t;
        case 7: return g_m1;
        case 8: return g_r1;
        default: return nullptr;
    }
}

// pixel index p = b*65536 + y*256 + x  ->  window-token index after roll(-4,-4)
// token(wi,wj,r,c) corresponds to pixel y=(wi*8+r+4)%256, x=(wj*8+c+4)%256
__device__ __forceinline__ int tok_of_pixel(int p) {
    int b = p >> 16;
    int y = (p >> 8) & 255;
    int x = p & 255;
    int i = (y + 252) & 255;  // (y-4) mod 256
    int j = (x + 252) & 255;
    int wi = i >> 3, r = i & 7;
    int wj = j >> 3, c = j & 7;
    return (((b << 10) | (wi << 5) | wj) << 6) | (r << 3) | c;
}

// ---------------------------------------------------------------------------
// Generic tiled SGEMM: C[M,N] = epilogue(A[M,K] @ W[K,N] + bias)
// BM=BN=128, BK=16, 256 threads, 8x8 per-thread micro-tile.
// gather: 0 = A rows contiguous (stride K); 1 = concat(convx[p], t[tok(p)])
// epi: 0 plain, 1 gelu, 2 +resid, 3 split->convx/tw (conv1), 4 +extra (conv2->out)
// ---------------------------------------------------------------------------
#define GA_NONE   0
#define GA_CONCAT 1
#define EPI_PLAIN 0
#define EPI_GELU  1
#define EPI_RESID 2
#define EPI_SPLIT 3
#define EPI_ADDX  4

__global__ __launch_bounds__(256) void gemm_kernel(
    const float* __restrict__ Aext, int asel,
    const float* __restrict__ W,
    const float* __restrict__ bias,
    const float* __restrict__ Rext, int rsel,
    const float* __restrict__ extra,
    float* __restrict__ Cext, int csel,
    int N, int K, int gather, int epi)
{
    const float* A = asel ? sel_buf(asel) : Aext;
    const float* R = rsel ? sel_buf(rsel) : Rext;
    float* C = csel ? sel_buf(csel) : Cext;

    __shared__ __align__(16) float As[16][132];
    __shared__ __align__(16) float Bs[16][128];

    const int bm = blockIdx.y << 7;
    const int bn = blockIdx.x << 7;
    const int tid = threadIdx.x;
    const int ty = tid >> 4, tx = tid & 15;

    float acc[8][8];
#pragma unroll
    for (int i = 0; i < 8; i++)
#pragma unroll
        for (int j = 0; j < 8; j++) acc[i][j] = 0.f;

    for (int k0 = 0; k0 < K; k0 += 16) {
        // load A tile (128 rows x 16 k), transposed into As[k][m]
#pragma unroll
        for (int l = 0; l < 2; l++) {
            int f = tid + (l << 8);
            int row = f >> 2;
            int kk4 = (f & 3) << 2;
            int m = bm + row;
            int k = k0 + kk4;
            float4 v;
            if (gather == GA_NONE) {
                v = *(const float4*)(A + (size_t)m * K + k);
            } else { // concat: k<128 -> convx[p], else t[tok(p)]
                if (k < 128) {
                    v = *(const float4*)(g_convx + (size_t)m * 128 + k);
                } else {
                    int tk = tok_of_pixel(m);
                    v = *(const float4*)(g_t + (size_t)tk * 128 + (k - 128));
                }
            }
            As[kk4 + 0][row] = v.x;
            As[kk4 + 1][row] = v.y;
            As[kk4 + 2][row] = v.z;
            As[kk4 + 3][row] = v.w;
        }
        // load B tile (16 k x 128 n)
#pragma unroll
        for (int l = 0; l < 2; l++) {
            int f = tid + (l << 8);
            int kk = f >> 5;
            int c4 = (f & 31) << 2;
            *(float4*)&Bs[kk][c4] = *(const float4*)(W + (size_t)(k0 + kk) * N + bn + c4);
        }
        __syncthreads();
#pragma unroll
        for (int kk = 0; kk < 16; kk++) {
            float4 a0 = *(const float4*)&As[kk][ty * 8];
            float4 a1 = *(const float4*)&As[kk][ty * 8 + 4];
            float4 b0 = *(const float4*)&Bs[kk][tx * 8];
            float4 b1 = *(const float4*)&Bs[kk][tx * 8 + 4];
            float a[8] = {a0.x, a0.y, a0.z, a0.w, a1.x, a1.y, a1.z, a1.w};
            float b[8] = {b0.x, b0.y, b0.z, b0.w, b1.x, b1.y, b1.z, b1.w};
#pragma unroll
            for (int i = 0; i < 8; i++)
#pragma unroll
                for (int j = 0; j < 8; j++) acc[i][j] += a[i] * b[j];
        }
        __syncthreads();
    }

    // epilogue
#pragma unroll
    for (int i = 0; i < 8; i++) {
        const int m = bm + ty * 8 + i;
        if (epi == EPI_SPLIT) {
            const size_t twbase = (size_t)tok_of_pixel(m) * 128;
#pragma unroll
            for (int j = 0; j < 8; j++) {
                const int n = bn + tx * 8 + j;
                float v = acc[i][j] + bias[n];
                if (n < 128) g_convx[(size_t)m * 128 + n] = v;
                else         g_tw[twbase + (n - 128)] = v;
            }
        } else {
#pragma unroll
            for (int j = 0; j < 8; j++) {
                const int n = bn + tx * 8 + j;
                float v = acc[i][j] + bias[n];
                const size_t idx = (size_t)m * N + n;
                if (epi == EPI_GELU) {
                    v = 0.5f * v * (1.f + erff(v * 0.70710678118654752f));
                } else if (epi == EPI_RESID) {
                    v += R[idx];
                } else if (epi == EPI_ADDX) {
                    v += extra[idx];
                }
                C[idx] = v;
            }
        }
    }
}

// ---------------------------------------------------------------------------
// 3x3 conv (SAME), implicit GEMM. 128 contiguous pixels per block (all share
// one image row since W=256), all 128 output channels. K-loop = 9 taps x 8
// chunks of 16 input channels. Epilogue: lrelu then optional +scale*resid.
// ---------------------------------------------------------------------------
__global__ __launch_bounds__(256) void conv3_kernel(
    int insel, const float* __restrict__ W,
    const float* __restrict__ bias,
    int rsel, float rscale, int osel)
{
    const float* in = sel_buf(insel);
    const float* R = rsel ? sel_buf(rsel) : nullptr;
    float* out = sel_buf(osel);

    __shared__ __align__(16) float As[16][132];
    __shared__ __align__(16) float Bs[16][128];

    const int bm = blockIdx.x << 7;
    const int b = bm >> 16;
    const int y = (bm >> 8) & 255;
    const int x0 = bm & 255;
    const int tid = threadIdx.x;
    const int ty = tid >> 4, tx = tid & 15;

    float acc[8][8];
#pragma unroll
    for (int i = 0; i < 8; i++)
#pragma unroll
        for (int j = 0; j < 8; j++) acc[i][j] = 0.f;

    for (int tap = 0; tap < 9; tap++) {
        const int dy = tap / 3 - 1;
        const int dx = tap % 3 - 1;
        const int yy = y + dy;
        const bool rowok = ((unsigned)yy < 256u);
        for (int kc = 0; kc < 128; kc += 16) {
#pragma unroll
            for (int l = 0; l < 2; l++) {
                int f = tid + (l << 8);
                int row = f >> 2;
                int kk4 = (f & 3) << 2;
                int xx = x0 + row + dx;
                float4 v = make_float4(0.f, 0.f, 0.f, 0.f);
                if (rowok && (unsigned)xx < 256u) {
                    size_t idx = ((size_t)((b * 256 + yy) * 256 + xx)) * 128 + kc + kk4;
                    v = *(const float4*)(in + idx);
                }
                As[kk4 + 0][row] = v.x;
                As[kk4 + 1][row] = v.y;
                As[kk4 + 2][row] = v.z;
                As[kk4 + 3][row] = v.w;
            }
#pragma unroll
            for (int l = 0; l < 2; l++) {
                int f = tid + (l << 8);
                int kk = f >> 5;
                int c4 = (f & 31) << 2;
                *(float4*)&Bs[kk][c4] =
                    *(const float4*)(W + (size_t)(tap * 128 + kc + kk) * 128 + c4);
            }
            __syncthreads();
#pragma unroll
            for (int kk = 0; kk < 16; kk++) {
                float4 a0 = *(const float4*)&As[kk][ty * 8];
                float4 a1 = *(const float4*)&As[kk][ty * 8 + 4];
                float4 b0 = *(const float4*)&Bs[kk][tx * 8];
                float4 b1 = *(const float4*)&Bs[kk][tx * 8 + 4];
                float a[8] = {a0.x, a0.y, a0.z, a0.w, a1.x, a1.y, a1.z, a1.w};
                float bb[8] = {b0.x, b0.y, b0.z, b0.w, b1.x, b1.y, b1.z, b1.w};
#pragma unroll
                for (int i = 0; i < 8; i++)
#pragma unroll
                    for (int j = 0; j < 8; j++) acc[i][j] += a[i] * bb[j];
            }
            __syncthreads();
        }
    }

#pragma unroll
    for (int i = 0; i < 8; i++) {
        const size_t m = (size_t)bm + ty * 8 + i;
#pragma unroll
        for (int j = 0; j < 8; j++) {
            const int n = tx * 8 + j;
            float v = acc[i][j] + bias[n];
            v = (v >= 0.f) ? v : 0.01f * v;
            if (R) v += rscale * R[m * 128 + n];
            out[m * 128 + n] = v;
        }
    }
}

// ---------------------------------------------------------------------------
// LayerNorm over 128 channels; 1 warp per row, 8 rows per block.
// ---------------------------------------------------------------------------
__global__ __launch_bounds__(256) void ln_kernel(
    int insel, const float* __restrict__ gamma,
    const float* __restrict__ beta, int osel)
{
    const float* in = sel_buf(insel);
    float* out = sel_buf(osel);
    const int row = blockIdx.x * 8 + (threadIdx.x >> 5);
    const int lane = threadIdx.x & 31;
    const float4 v = *(const float4*)(in + (size_t)row * 128 + lane * 4);
    float sum = v.x + v.y + v.z + v.w;
    float sq = v.x * v.x + v.y * v.y + v.z * v.z + v.w * v.w;
#pragma unroll
    for (int off = 16; off > 0; off >>= 1) {
        sum += __shfl_xor_sync(0xffffffffu, sum, off);
        sq  += __shfl_xor_sync(0xffffffffu, sq, off);
    }
    const float mean = sum * 0.0078125f;
    const float var = sq * 0.0078125f - mean * mean;
    const float rstd = rsqrtf(var + 1e-5f);
    const float4 g4 = *(const float4*)(gamma + lane * 4);
    const float4 b4 = *(const float4*)(beta + lane * 4);
    float4 o;
    o.x = (v.x - mean) * rstd * g4.x + b4.x;
    o.y = (v.y - mean) * rstd * g4.y + b4.y;
    o.z = (v.z - mean) * rstd * g4.z + b4.z;
    o.w = (v.w - mean) * rstd * g4.w + b4.w;
    *(float4*)(out + (size_t)row * 128 + lane * 4) = o;
}

// ---------------------------------------------------------------------------
// Windowed attention: 1 block per (batch, window) = 2048 blocks, 256 threads.
// Thread t handles (head = t/64, query = t%64). Scores/softmax in registers;
// K then V staged through the same smem buffer (two phases).
// ---------------------------------------------------------------------------
__global__ __launch_bounds__(256) void attn_kernel(const float* __restrict__ rpb)
{
    __shared__ __align__(16) float skv[64][128];
    __shared__ float srpb[900];

    const int wid = blockIdx.x;          // b*1024 + wi*32 + wj
    const int wi = (wid >> 5) & 31;
    const int wj = wid & 31;
    const size_t tokbase = (size_t)wid * 64;
    const float* qkvp = g_qkv + tokbase * 384;
    const int tid = threadIdx.x;

    // load K (cols 128..255 of qkv)
#pragma unroll
    for (int l = 0; l < 8; l++) {
        int f = tid + (l << 8);
        int j = f >> 5;
        int c4 = (f & 31) << 2;
        *(float4*)&skv[j][c4] = *(const float4*)(qkvp + (size_t)j * 384 + 128 + c4);
    }
    for (int f = tid; f < 900; f += 256) srpb[f] = rpb[f];
    __syncthreads();

    const int head = tid >> 6;
    const int i = tid & 63;
    const int hb = head << 5;

    float q[32];
    {
        const float* qp = qkvp + (size_t)i * 384 + hb;
#pragma unroll
        for (int d4 = 0; d4 < 8; d4++) {
            float4 v = *(const float4*)(qp + 4 * d4);
            q[4 * d4 + 0] = v.x; q[4 * d4 + 1] = v.y;
            q[4 * d4 + 2] = v.z; q[4 * d4 + 3] = v.w;
        }
    }
    const int ri = i >> 3, ci = i & 7;
    const int gi = ((wi == 31) ? (ri < 4 ? 1 : 2) : 0) * 3
                 + ((wj == 31) ? (ci < 4 ? 1 : 2) : 0);

    float s[64];
#pragma unroll
    for (int j = 0; j < 64; j++) {
        float dot = 0.f;
#pragma unroll
        for (int d4 = 0; d4 < 8; d4++) {
            float4 kv = *(const float4*)&skv[j][hb + 4 * d4];
            dot += q[4 * d4 + 0] * kv.x;
            dot += q[4 * d4 + 1] * kv.y;
            dot += q[4 * d4 + 2] * kv.z;
            dot += q[4 * d4 + 3] * kv.w;
        }
        const int rj = j >> 3, cj = j & 7;
        const int gj = ((wi == 31) ? (rj < 4 ? 1 : 2) : 0) * 3
                     + ((wj == 31) ? (cj < 4 ? 1 : 2) : 0);
        const float bias = srpb[((ri - rj + 7) * 15 + (ci - cj + 7)) * 4 + head];
        const float msk = (gi == gj) ? 0.f : -1000000000.f;
        s[j] = dot * 0.17677669529663689f + bias + msk;
    }

    float mx = s[0];
#pragma unroll
    for (int j = 1; j < 64; j++) mx = fmaxf(mx, s[j]);
    float sum = 0.f;
#pragma unroll
    for (int j = 0; j < 64; j++) { s[j] = __expf(s[j] - mx); sum += s[j]; }
    const float inv = 1.f / sum;

    __syncthreads();  // all threads done reading K
    // load V (cols 256..383)
#pragma unroll
    for (int l = 0; l < 8; l++) {
        int f = tid + (l << 8);
        int j = f >> 5;
        int c4 = (f & 31) << 2;
        *(float4*)&skv[j][c4] = *(const float4*)(qkvp + (size_t)j * 384 + 256 + c4);
    }
    __syncthreads();

    float o[32];
#pragma unroll
    for (int d = 0; d < 32; d++) o[d] = 0.f;
#pragma unroll
    for (int j = 0; j < 64; j++) {
        const float a = s[j];
#pragma unroll
        for (int d4 = 0; d4 < 8; d4++) {
            float4 vv = *(const float4*)&skv[j][hb + 4 * d4];
            o[4 * d4 + 0] += a * vv.x;
            o[4 * d4 + 1] += a * vv.y;
            o[4 * d4 + 2] += a * vv.z;
            o[4 * d4 + 3] += a * vv.w;
        }
    }
    float* op = g_attnout + (tokbase + i) * 128 + hb;
#pragma unroll
    for (int d4 = 0; d4 < 8; d4++) {
        float4 v = make_float4(o[4 * d4 + 0] * inv, o[4 * d4 + 1] * inv,
                               o[4 * d4 + 2] * inv, o[4 * d4 + 3] * inv);
        *(float4*)(op + 4 * d4) = v;
    }
}

// ---------------------------------------------------------------------------
// Launch orchestration
// ---------------------------------------------------------------------------
extern "C" void kernel_launch(void* const* d_in, const int* in_sizes, int n_in,
                              void* d_out, int out_size)
{
    (void)in_sizes; (void)n_in; (void)out_size;
    const float* x    = (const float*)d_in[0];
    const float* c1w  = (const float*)d_in[1];
    const float* c1b  = (const float*)d_in[2];
    const float* rw1  = (const float*)d_in[3];
    const float* rb1  = (const float*)d_in[4];
    const float* rw2  = (const float*)d_in[5];
    const float* rb2  = (const float*)d_in[6];
    const float* ln1g = (const float*)d_in[7];
    const float* ln1b = (const float*)d_in[8];
    const float* qkvw = (const float*)d_in[9];
    const float* qkvb = (const float*)d_in[10];
    const float* rpb  = (const float*)d_in[11];
    const float* pw   = (const float*)d_in[12];
    const float* pb   = (const float*)d_in[13];
    const float* ln2g = (const float*)d_in[14];
    const float* ln2b = (const float*)d_in[15];
    const float* mw1  = (const float*)d_in[16];
    const float* mb1  = (const float*)d_in[17];
    const float* mw2  = (const float*)d_in[18];
    const float* mb2  = (const float*)d_in[19];
    const float* c2w  = (const float*)d_in[20];
    const float* c2b  = (const float*)d_in[21];
    float* out = (float*)d_out;

    const dim3 blk(256);
    const int MB = PIX / 128;  // 1024 M-tiles

    // 1. conv1 (1x1): y = x @ c1w + c1b; split -> g_convx (pixel order),
    //    g_tw (window-token order, rolled by -SHIFT)
    gemm_kernel<<<dim3(2, MB), blk>>>(x, 0, c1w, c1b, nullptr, 0, nullptr,
                                      nullptr, 0, 256, 256, GA_NONE, EPI_SPLIT);
    // 2. r1 = lrelu(conv3x3(convx, rw1) + rb1)
    conv3_kernel<<<MB, blk>>>(1, rw1, rb1, 0, 0.f, 8);
    // 3. convx = lrelu(conv3x3(r1, rw2) + rb2) + 2*convx   (in-place residual)
    conv3_kernel<<<MB, blk>>>(8, rw2, rb2, 1, 2.f, 1);
    // 4. h = LN1(tw)
    ln_kernel<<<PIX / 8, blk>>>(2, ln1g, ln1b, 3);
    // 5. qkv = h @ qkvw + qkvb
    gemm_kernel<<<dim3(3, MB), blk>>>(nullptr, 3, qkvw, qkvb, nullptr, 0, nullptr,
                                      nullptr, 4, 384, 128, GA_NONE, EPI_PLAIN);
    // 6. windowed attention -> g_attnout
    attn_kernel<<<2048, blk>>>(rpb);
    // 7. t = attnout @ pw + pb + tw
    gemm_kernel<<<dim3(1, MB), blk>>>(nullptr, 5, pw, pb, nullptr, 2, nullptr,
                                      nullptr, 6, 128, 128, GA_NONE, EPI_RESID);
    // 8. h = LN2(t)
    ln_kernel<<<PIX / 8, blk>>>(6, ln2g, ln2b, 3);
    // 9. m1 = gelu(h @ mw1 + mb1)
    gemm_kernel<<<dim3(4, MB), blk>>>(nullptr, 3, mw1, mb1, nullptr, 0, nullptr,
                                      nullptr, 7, 512, 128, GA_NONE, EPI_GELU);
    // 10. t = m1 @ mw2 + mb2 + t   (in-place, element-wise 1:1, safe)
    gemm_kernel<<<dim3(1, MB), blk>>>(nullptr, 7, mw2, mb2, nullptr, 6, nullptr,
                                      nullptr, 6, 128, 512, GA_NONE, EPI_RESID);
    // 11. out = concat(convx, t[tok(p)]) @ c2w + c2b + x
    gemm_kernel<<<dim3(2, MB), blk>>>(nullptr, 0, c2w, c2b, nullptr, 0, x,
                                      out, 0, 256, 256, GA_CONCAT, EPI_ADDX);
}

// round 7
// speedup vs baseline: 1.0061x; 1.0038x over previous
#include <cuda_runtime.h>
#include <math.h>

// ---------------------------------------------------------------------------
// Problem constants
// B=2, H=W=256, C=256, CD=128, TD=128, HD=32, NH=4, WS=8, SHIFT=4
// PIX = B*H*W = 131072 pixel-tokens. All token tensors are [PIX, ch].
// ---------------------------------------------------------------------------
#define PIX 131072

// Scratch buffers (static device globals; allocation-free per harness rules)
__device__ float g_convx[(size_t)PIX * 128];   // conv path features (pixel order)
__device__ float g_r1[(size_t)PIX * 128];      // conv3x3 intermediate
__device__ float g_tw[(size_t)PIX * 128];      // trans features, window-token order
__device__ float g_h[(size_t)PIX * 128];       // layernorm output (reused ln1/ln2)
__device__ float g_qkv[(size_t)PIX * 384];     // qkv, window-token order
__device__ float g_attnout[(size_t)PIX * 128]; // attention output, window-token order
__device__ float g_t[(size_t)PIX * 128];       // transformer residual stream
__device__ float g_m1[(size_t)PIX * 512];      // mlp hidden

__device__ __forceinline__ float* sel_buf(int s) {
    switch (s) {
        case 1: return g_convx;
        case 2: return g_tw;
        case 3: return g_h;
        case 4: return g_qkv;
        case 5: return g_attnout;
        case 6: return g_t;
        case 7: return g_m1;
        case 8: return g_r1;
        default: return nullptr;
    }
}

// pixel index p = b*65536 + y*256 + x  ->  window-token index after roll(-4,-4)
// token(wi,wj,r,c) corresponds to pixel y=(wi*8+r+4)%256, x=(wj*8+c+4)%256
__device__ __forceinline__ int tok_of_pixel(int p) {
    int b = p >> 16;
    int y = (p >> 8) & 255;
    int x = p & 255;
    int i = (y + 252) & 255;  // (y-4) mod 256
    int j = (x + 252) & 255;
    int wi = i >> 3, r = i & 7;
    int wj = j >> 3, c = j & 7;
    return (((b << 10) | (wi << 5) | wj) << 6) | (r << 3) | c;
}

// ---------------------------------------------------------------------------
// Generic tiled SGEMM: C[M,N] = epilogue(A[M,K] @ W[K,N] + bias)
// BM=BN=128, BK=16, 256 threads, 8x8 per-thread micro-tile.
// gather: 0 = A rows contiguous (stride K); 1 = concat(convx[p], t[tok(p)])
// epi: 0 plain, 1 gelu, 2 +resid, 3 split->convx/tw (conv1), 4 +extra (conv2->out)
// ---------------------------------------------------------------------------
#define GA_NONE   0
#define GA_CONCAT 1
#define EPI_PLAIN 0
#define EPI_GELU  1
#define EPI_RESID 2
#define EPI_SPLIT 3
#define EPI_ADDX  4

__global__ __launch_bounds__(256) void gemm_kernel(
    const float* __restrict__ Aext, int asel,
    const float* __restrict__ W,
    const float* __restrict__ bias,
    const float* __restrict__ Rext, int rsel,
    const float* __restrict__ extra,
    float* __restrict__ Cext, int csel,
    int N, int K, int gather, int epi)
{
    const float* A = asel ? sel_buf(asel) : Aext;
    const float* R = rsel ? sel_buf(rsel) : Rext;
    float* C = csel ? sel_buf(csel) : Cext;

    __shared__ __align__(16) float As[16][132];
    __shared__ __align__(16) float Bs[16][128];

    const int bm = blockIdx.y << 7;
    const int bn = blockIdx.x << 7;
    const int tid = threadIdx.x;
    const int ty = tid >> 4, tx = tid & 15;

    float acc[8][8];
#pragma unroll
    for (int i = 0; i < 8; i++)
#pragma unroll
        for (int j = 0; j < 8; j++) acc[i][j] = 0.f;

    for (int k0 = 0; k0 < K; k0 += 16) {
        // load A tile (128 rows x 16 k), transposed into As[k][m]
#pragma unroll
        for (int l = 0; l < 2; l++) {
            int f = tid + (l << 8);
            int row = f >> 2;
            int kk4 = (f & 3) << 2;
            int m = bm + row;
            int k = k0 + kk4;
            float4 v;
            if (gather == GA_NONE) {
                v = *(const float4*)(A + (size_t)m * K + k);
            } else { // concat: k<128 -> convx[p], else t[tok(p)]
                if (k < 128) {
                    v = *(const float4*)(g_convx + (size_t)m * 128 + k);
                } else {
                    int tk = tok_of_pixel(m);
                    v = *(const float4*)(g_t + (size_t)tk * 128 + (k - 128));
                }
            }
            As[kk4 + 0][row] = v.x;
            As[kk4 + 1][row] = v.y;
            As[kk4 + 2][row] = v.z;
            As[kk4 + 3][row] = v.w;
        }
        // load B tile (16 k x 128 n)
#pragma unroll
        for (int l = 0; l < 2; l++) {
            int f = tid + (l << 8);
            int kk = f >> 5;
            int c4 = (f & 31) << 2;
            *(float4*)&Bs[kk][c4] = *(const float4*)(W + (size_t)(k0 + kk) * N + bn + c4);
        }
        __syncthreads();
#pragma unroll
        for (int kk = 0; kk < 16; kk++) {
            float4 a0 = *(const float4*)&As[kk][ty * 8];
            float4 a1 = *(const float4*)&As[kk][ty * 8 + 4];
            float4 b0 = *(const float4*)&Bs[kk][tx * 8];
            float4 b1 = *(const float4*)&Bs[kk][tx * 8 + 4];
            float a[8] = {a0.x, a0.y, a0.z, a0.w, a1.x, a1.y, a1.z, a1.w};
            float b[8] = {b0.x, b0.y, b0.z, b0.w, b1.x, b1.y, b1.z, b1.w};
#pragma unroll
            for (int i = 0; i < 8; i++)
#pragma unroll
                for (int j = 0; j < 8; j++) acc[i][j] += a[i] * b[j];
        }
        __syncthreads();
    }

    // epilogue
#pragma unroll
    for (int i = 0; i < 8; i++) {
        const int m = bm + ty * 8 + i;
        if (epi == EPI_SPLIT) {
            const size_t twbase = (size_t)tok_of_pixel(m) * 128;
#pragma unroll
            for (int j = 0; j < 8; j++) {
                const int n = bn + tx * 8 + j;
                float v = acc[i][j] + bias[n];
                if (n < 128) g_convx[(size_t)m * 128 + n] = v;
                else         g_tw[twbase + (n - 128)] = v;
            }
        } else {
#pragma unroll
            for (int j = 0; j < 8; j++) {
                const int n = bn + tx * 8 + j;
                float v = acc[i][j] + bias[n];
                const size_t idx = (size_t)m * N + n;
                if (epi == EPI_GELU) {
                    v = 0.5f * v * (1.f + erff(v * 0.70710678118654752f));
                } else if (epi == EPI_RESID) {
                    v += R[idx];
                } else if (epi == EPI_ADDX) {
                    v += extra[idx];
                }
                C[idx] = v;
            }
        }
    }
}

// ---------------------------------------------------------------------------
// 3x3 conv (SAME), implicit GEMM. 128 contiguous pixels per block (all share
// one image row since W=256), all 128 output channels. K-loop = 9 taps x 8
// chunks of 16 input channels. Epilogue: lrelu then optional +scale*resid.
// ---------------------------------------------------------------------------
__global__ __launch_bounds__(256) void conv3_kernel(
    int insel, const float* __restrict__ W,
    const float* __restrict__ bias,
    int rsel, float rscale, int osel)
{
    const float* in = sel_buf(insel);
    const float* R = rsel ? sel_buf(rsel) : nullptr;
    float* out = sel_buf(osel);

    __shared__ __align__(16) float As[16][132];
    __shared__ __align__(16) float Bs[16][128];

    const int bm = blockIdx.x << 7;
    const int b = bm >> 16;
    const int y = (bm >> 8) & 255;
    const int x0 = bm & 255;
    const int tid = threadIdx.x;
    const int ty = tid >> 4, tx = tid & 15;

    float acc[8][8];
#pragma unroll
    for (int i = 0; i < 8; i++)
#pragma unroll
        for (int j = 0; j < 8; j++) acc[i][j] = 0.f;

    for (int tap = 0; tap < 9; tap++) {
        const int dy = tap / 3 - 1;
        const int dx = tap % 3 - 1;
        const int yy = y + dy;
        const bool rowok = ((unsigned)yy < 256u);
        for (int kc = 0; kc < 128; kc += 16) {
#pragma unroll
            for (int l = 0; l < 2; l++) {
                int f = tid + (l << 8);
                int row = f >> 2;
                int kk4 = (f & 3) << 2;
                int xx = x0 + row + dx;
                float4 v = make_float4(0.f, 0.f, 0.f, 0.f);
                if (rowok && (unsigned)xx < 256u) {
                    size_t idx = ((size_t)((b * 256 + yy) * 256 + xx)) * 128 + kc + kk4;
                    v = *(const float4*)(in + idx);
                }
                As[kk4 + 0][row] = v.x;
                As[kk4 + 1][row] = v.y;
                As[kk4 + 2][row] = v.z;
                As[kk4 + 3][row] = v.w;
            }
#pragma unroll
            for (int l = 0; l < 2; l++) {
                int f = tid + (l << 8);
                int kk = f >> 5;
                int c4 = (f & 31) << 2;
                *(float4*)&Bs[kk][c4] =
                    *(const float4*)(W + (size_t)(tap * 128 + kc + kk) * 128 + c4);
            }
            __syncthreads();
#pragma unroll
            for (int kk = 0; kk < 16; kk++) {
                float4 a0 = *(const float4*)&As[kk][ty * 8];
                float4 a1 = *(const float4*)&As[kk][ty * 8 + 4];
                float4 b0 = *(const float4*)&Bs[kk][tx * 8];
                float4 b1 = *(const float4*)&Bs[kk][tx * 8 + 4];
                float a[8] = {a0.x, a0.y, a0.z, a0.w, a1.x, a1.y, a1.z, a1.w};
                float bb[8] = {b0.x, b0.y, b0.z, b0.w, b1.x, b1.y, b1.z, b1.w};
#pragma unroll
                for (int i = 0; i < 8; i++)
#pragma unroll
                    for (int j = 0; j < 8; j++) acc[i][j] += a[i] * bb[j];
            }
            __syncthreads();
        }
    }

#pragma unroll
    for (int i = 0; i < 8; i++) {
        const size_t m = (size_t)bm + ty * 8 + i;
#pragma unroll
        for (int j = 0; j < 8; j++) {
            const int n = tx * 8 + j;
            float v = acc[i][j] + bias[n];
            v = (v >= 0.f) ? v : 0.01f * v;
            if (R) v += rscale * R[m * 128 + n];
            out[m * 128 + n] = v;
        }
    }
}

// ---------------------------------------------------------------------------
// LayerNorm over 128 channels; 1 warp per row, 8 rows per block.
// ---------------------------------------------------------------------------
__global__ __launch_bounds__(256) void ln_kernel(
    int insel, const float* __restrict__ gamma,
    const float* __restrict__ beta, int osel)
{
    const float* in = sel_buf(insel);
    float* out = sel_buf(osel);
    const int row = blockIdx.x * 8 + (threadIdx.x >> 5);
    const int lane = threadIdx.x & 31;
    const float4 v = *(const float4*)(in + (size_t)row * 128 + lane * 4);
    float sum = v.x + v.y + v.z + v.w;
    float sq = v.x * v.x + v.y * v.y + v.z * v.z + v.w * v.w;
#pragma unroll
    for (int off = 16; off > 0; off >>= 1) {
        sum += __shfl_xor_sync(0xffffffffu, sum, off);
        sq  += __shfl_xor_sync(0xffffffffu, sq, off);
    }
    const float mean = sum * 0.0078125f;
    const float var = sq * 0.0078125f - mean * mean;
    const float rstd = rsqrtf(var + 1e-5f);
    const float4 g4 = *(const float4*)(gamma + lane * 4);
    const float4 b4 = *(const float4*)(beta + lane * 4);
    float4 o;
    o.x = (v.x - mean) * rstd * g4.x + b4.x;
    o.y = (v.y - mean) * rstd * g4.y + b4.y;
    o.z = (v.z - mean) * rstd * g4.z + b4.z;
    o.w = (v.w - mean) * rstd * g4.w + b4.w;
    *(float4*)(out + (size_t)row * 128 + lane * 4) = o;
}

// ---------------------------------------------------------------------------
// Windowed attention: 1 block per (batch, window) = 2048 blocks, 256 threads.
// Thread t handles (head = t/64, query = t%64). Scores/softmax in registers;
// K then V staged through the same smem buffer (two phases).
// ---------------------------------------------------------------------------
__global__ __launch_bounds__(256) void attn_kernel(const float* __restrict__ rpb)
{
    __shared__ __align__(16) float skv[64][128];
    __shared__ float srpb[900];

    const int wid = blockIdx.x;          // b*1024 + wi*32 + wj
    const int wi = (wid >> 5) & 31;
    const int wj = wid & 31;
    const size_t tokbase = (size_t)wid * 64;
    const float* qkvp = g_qkv + tokbase * 384;
    const int tid = threadIdx.x;

    // load K (cols 128..255 of qkv)
#pragma unroll
    for (int l = 0; l < 8; l++) {
        int f = tid + (l << 8);
        int j = f >> 5;
        int c4 = (f & 31) << 2;
        *(float4*)&skv[j][c4] = *(const float4*)(qkvp + (size_t)j * 384 + 128 + c4);
    }
    for (int f = tid; f < 900; f += 256) srpb[f] = rpb[f];
    __syncthreads();

    const int head = tid >> 6;
    const int i = tid & 63;
    const int hb = head << 5;

    float q[32];
    {
        const float* qp = qkvp + (size_t)i * 384 + hb;
#pragma unroll
        for (int d4 = 0; d4 < 8; d4++) {
            float4 v = *(const float4*)(qp + 4 * d4);
            q[4 * d4 + 0] = v.x; q[4 * d4 + 1] = v.y;
            q[4 * d4 + 2] = v.z; q[4 * d4 + 3] = v.w;
        }
    }
    const int ri = i >> 3, ci = i & 7;
    const int gi = ((wi == 31) ? (ri < 4 ? 1 : 2) : 0) * 3
                 + ((wj == 31) ? (ci < 4 ? 1 : 2) : 0);

    float s[64];
#pragma unroll
    for (int j = 0; j < 64; j++) {
        float dot = 0.f;
#pragma unroll
        for (int d4 = 0; d4 < 8; d4++) {
            float4 kv = *(const float4*)&skv[j][hb + 4 * d4];
            dot += q[4 * d4 + 0] * kv.x;
            dot += q[4 * d4 + 1] * kv.y;
            dot += q[4 * d4 + 2] * kv.z;
            dot += q[4 * d4 + 3] * kv.w;
        }
        const int rj = j >> 3, cj = j & 7;
        const int gj = ((wi == 31) ? (rj < 4 ? 1 : 2) : 0) * 3
                     + ((wj == 31) ? (cj < 4 ? 1 : 2) : 0);
        const float bias = srpb[((ri - rj + 7) * 15 + (ci - cj + 7)) * 4 + head];
        const float msk = (gi == gj) ? 0.f : -1000000000.f;
        s[j] = dot * 0.17677669529663689f + bias + msk;
    }

    float mx = s[0];
#pragma unroll
    for (int j = 1; j < 64; j++) mx = fmaxf(mx, s[j]);
    float sum = 0.f;
#pragma unroll
    for (int j = 0; j < 64; j++) { s[j] = __expf(s[j] - mx); sum += s[j]; }
    const float inv = 1.f / sum;

    __syncthreads();  // all threads done reading K
    // load V (cols 256..383)
#pragma unroll
    for (int l = 0; l < 8; l++) {
        int f = tid + (l << 8);
        int j = f >> 5;
        int c4 = (f & 31) << 2;
        *(float4*)&skv[j][c4] = *(const float4*)(qkvp + (size_t)j * 384 + 256 + c4);
    }
    __syncthreads();

    float o[32];
#pragma unroll
    for (int d = 0; d < 32; d++) o[d] = 0.f;
#pragma unroll
    for (int j = 0; j < 64; j++) {
        const float a = s[j];
#pragma unroll
        for (int d4 = 0; d4 < 8; d4++) {
            float4 vv = *(const float4*)&skv[j][hb + 4 * d4];
            o[4 * d4 + 0] += a * vv.x;
            o[4 * d4 + 1] += a * vv.y;
            o[4 * d4 + 2] += a * vv.z;
            o[4 * d4 + 3] += a * vv.w;
        }
    }
    float* op = g_attnout + (tokbase + i) * 128 + hb;
#pragma unroll
    for (int d4 = 0; d4 < 8; d4++) {
        float4 v = make_float4(o[4 * d4 + 0] * inv, o[4 * d4 + 1] * inv,
                               o[4 * d4 + 2] * inv, o[4 * d4 + 3] * inv);
        *(float4*)(op + 4 * d4) = v;
    }
}

// ---------------------------------------------------------------------------
// Launch orchestration
// ---------------------------------------------------------------------------
extern "C" void kernel_launch(void* const* d_in, const int* in_sizes, int n_in,
                              void* d_out, int out_size)
{
    (void)in_sizes; (void)n_in; (void)out_size;
    const float* x    = (const float*)d_in[0];
    const float* c1w  = (const float*)d_in[1];
    const float* c1b  = (const float*)d_in[2];
    const float* rw1  = (const float*)d_in[3];
    const float* rb1  = (const float*)d_in[4];
    const float* rw2  = (const float*)d_in[5];
    const float* rb2  = (const float*)d_in[6];
    const float* ln1g = (const float*)d_in[7];
    const float* ln1b = (const float*)d_in[8];
    const float* qkvw = (const float*)d_in[9];
    const float* qkvb = (const float*)d_in[10];
    const float* rpb  = (const float*)d_in[11];
    const float* pw   = (const float*)d_in[12];
    const float* pb   = (const float*)d_in[13];
    const float* ln2g = (const float*)d_in[14];
    const float* ln2b = (const float*)d_in[15];
    const float* mw1  = (const float*)d_in[16];
    const float* mb1  = (const float*)d_in[17];
    const float* mw2  = (const float*)d_in[18];
    const float* mb2  = (const float*)d_in[19];
    const float* c2w  = (const float*)d_in[20];
    const float* c2b  = (const float*)d_in[21];
    float* out = (float*)d_out;

    const dim3 blk(256);
    const int MB = PIX / 128;  // 1024 M-tiles

    // 1. conv1 (1x1): y = x @ c1w + c1b; split -> g_convx (pixel order),
    //    g_tw (window-token order, rolled by -SHIFT)
    gemm_kernel<<<dim3(2, MB), blk>>>(x, 0, c1w, c1b, nullptr, 0, nullptr,
                                      nullptr, 0, 256, 256, GA_NONE, EPI_SPLIT);
    // 2. r1 = lrelu(conv3x3(convx, rw1) + rb1)
    conv3_kernel<<<MB, blk>>>(1, rw1, rb1, 0, 0.f, 8);
    // 3. convx = lrelu(conv3x3(r1, rw2) + rb2) + 2*convx   (in-place residual)
    conv3_kernel<<<MB, blk>>>(8, rw2, rb2, 1, 2.f, 1);
    // 4. h = LN1(tw)
    ln_kernel<<<PIX / 8, blk>>>(2, ln1g, ln1b, 3);
    // 5. qkv = h @ qkvw + qkvb
    gemm_kernel<<<dim3(3, MB), blk>>>(nullptr, 3, qkvw, qkvb, nullptr, 0, nullptr,
                                      nullptr, 4, 384, 128, GA_NONE, EPI_PLAIN);
    // 6. windowed attention -> g_attnout
    attn_kernel<<<2048, blk>>>(rpb);
    // 7. t = attnout @ pw + pb + tw
    gemm_kernel<<<dim3(1, MB), blk>>>(nullptr, 5, pw, pb, nullptr, 2, nullptr,
                                      nullptr, 6, 128, 128, GA_NONE, EPI_RESID);
    // 8. h = LN2(t)
    ln_kernel<<<PIX / 8, blk>>>(6, ln2g, ln2b, 3);
    // 9. m1 = gelu(h @ mw1 + mb1)
    gemm_kernel<<<dim3(4, MB), blk>>>(nullptr, 3, mw1, mb1, nullptr, 0, nullptr,
                                      nullptr, 7, 512, 128, GA_NONE, EPI_GELU);
    // 10. t = m1 @ mw2 + mb2 + t   (in-place, element-wise 1:1, safe)
    gemm_kernel<<<dim3(1, MB), blk>>>(nullptr, 7, mw2, mb2, nullptr, 6, nullptr,
                                      nullptr, 6, 128, 512, GA_NONE, EPI_RESID);
    // 11. out = concat(convx, t[tok(p)]) @ c2w + c2b + x
    gemm_kernel<<<dim3(2, MB), blk>>>(nullptr, 0, c2w, c2b, nullptr, 0, x,
                                      out, 0, 256, 256, GA_CONCAT, EPI_ADDX);
}